// round 2
// baseline (speedup 1.0000x reference)
#include <cuda_runtime.h>
#include <cstdint>

#define NN 100000
#define DD 256

// Scratch for support = x @ W (allocation-free rule: __device__ global array)
__device__ float g_support[(size_t)NN * DD];

// ---------------------------------------------------------------------------
// GEMM: support[NN, 256] = x[NN, 256] @ W[256, 256]
// 128x128 block tile, 8x8 per-thread microtile, K-chunk 8, 256 threads.
// ---------------------------------------------------------------------------
__global__ void __launch_bounds__(256) gemm_kernel(const float* __restrict__ A,
                                                   const float* __restrict__ B) {
    __shared__ float As[8][128];
    __shared__ float Bs[8][128];

    const int tid  = threadIdx.x;
    const int tx   = tid & 15;   // 0..15  (col group)
    const int ty   = tid >> 4;   // 0..15  (row group)
    const int row0 = blockIdx.y * 128;
    const int col0 = blockIdx.x * 128;

    // A-tile load mapping: 128 rows x 8 k, float4 per thread (2 threads/row)
    const int a_row = tid >> 1;          // 0..127
    const int a_k4  = (tid & 1) * 4;     // 0 or 4
    // B-tile load mapping: 8 k-rows x 128 cols, float4 per thread
    const int b_k   = tid >> 5;          // 0..7
    const int b_c   = (tid & 31) * 4;    // 0..124

    float acc[8][8];
#pragma unroll
    for (int i = 0; i < 8; i++)
#pragma unroll
        for (int j = 0; j < 8; j++) acc[i][j] = 0.0f;

    for (int k0 = 0; k0 < DD; k0 += 8) {
        // Load A tile (clamp row for the ragged last block; stores are guarded)
        int gr = row0 + a_row;
        gr = gr < NN ? gr : NN - 1;
        float4 av = *(const float4*)(A + (size_t)gr * DD + k0 + a_k4);
        As[a_k4 + 0][a_row] = av.x;
        As[a_k4 + 1][a_row] = av.y;
        As[a_k4 + 2][a_row] = av.z;
        As[a_k4 + 3][a_row] = av.w;
        // Load B tile
        float4 bv = *(const float4*)(B + (size_t)(k0 + b_k) * DD + col0 + b_c);
        *(float4*)&Bs[b_k][b_c] = bv;
        __syncthreads();

#pragma unroll
        for (int kk = 0; kk < 8; kk++) {
            float4 a0 = *(const float4*)&As[kk][ty * 4];
            float4 a1 = *(const float4*)&As[kk][64 + ty * 4];
            float4 b0 = *(const float4*)&Bs[kk][tx * 4];
            float4 b1 = *(const float4*)&Bs[kk][64 + tx * 4];
            float a[8] = {a0.x, a0.y, a0.z, a0.w, a1.x, a1.y, a1.z, a1.w};
            float b[8] = {b0.x, b0.y, b0.z, b0.w, b1.x, b1.y, b1.z, b1.w};
#pragma unroll
            for (int i = 0; i < 8; i++)
#pragma unroll
                for (int j = 0; j < 8; j++) acc[i][j] += a[i] * b[j];
        }
        __syncthreads();
    }

    // Store
#pragma unroll
    for (int i = 0; i < 8; i++) {
        int r = row0 + ((i < 4) ? (ty * 4 + i) : (64 + ty * 4 + (i - 4)));
        if (r < NN) {
            float4 v0 = make_float4(acc[i][0], acc[i][1], acc[i][2], acc[i][3]);
            float4 v1 = make_float4(acc[i][4], acc[i][5], acc[i][6], acc[i][7]);
            *(float4*)(g_support + (size_t)r * DD + col0 + tx * 4) = v0;
            *(float4*)(g_support + (size_t)r * DD + col0 + 64 + tx * 4) = v1;
        }
    }
}

// ---------------------------------------------------------------------------
// SpMM: out[row] += val * support[col] per edge, one warp per edge.
// Vector fp32 reduction (red.global.add.v4.f32, sm_90+) to quarter the
// L2 atomic op count vs scalar atomicAdd.
// ---------------------------------------------------------------------------
__device__ __forceinline__ void red_add_v4(float* addr, float4 v) {
    asm volatile("red.global.add.v4.f32 [%0], {%1, %2, %3, %4};"
                 :: "l"(addr), "f"(v.x), "f"(v.y), "f"(v.z), "f"(v.w)
                 : "memory");
}

__global__ void __launch_bounds__(256) spmm_kernel(const float* __restrict__ ev,
                                                   const int* __restrict__ er,
                                                   const int* __restrict__ ec,
                                                   float* __restrict__ out,
                                                   int E) {
    const int gw   = (blockIdx.x * 256 + threadIdx.x) >> 5;  // global warp = edge id
    const int lane = threadIdx.x & 31;
    if (gw >= E) return;

    const int   r = __ldg(er + gw);
    const int   c = __ldg(ec + gw);
    const float v = __ldg(ev + gw);

    const float4* s = (const float4*)(g_support + (size_t)c * DD);
    float4 m0 = s[lane];        // bytes [lane*16, ...)
    float4 m1 = s[lane + 32];   // second half of the 256-float row
    m0.x *= v; m0.y *= v; m0.z *= v; m0.w *= v;
    m1.x *= v; m1.y *= v; m1.z *= v; m1.w *= v;

    float* o = out + (size_t)r * DD;
    red_add_v4(o + lane * 4, m0);
    red_add_v4(o + 128 + lane * 4, m1);
}

// ---------------------------------------------------------------------------
// zero / relu epilogue passes
// ---------------------------------------------------------------------------
__global__ void __launch_bounds__(256) zero_kernel(float4* __restrict__ out, int n4) {
    int i = blockIdx.x * 256 + threadIdx.x;
    if (i < n4) out[i] = make_float4(0.f, 0.f, 0.f, 0.f);
}

__global__ void __launch_bounds__(256) relu_kernel(float4* __restrict__ out, int n4) {
    int i = blockIdx.x * 256 + threadIdx.x;
    if (i < n4) {
        float4 v = out[i];
        v.x = fmaxf(v.x, 0.f);
        v.y = fmaxf(v.y, 0.f);
        v.z = fmaxf(v.z, 0.f);
        v.w = fmaxf(v.w, 0.f);
        out[i] = v;
    }
}

// ---------------------------------------------------------------------------
// Launch
// ---------------------------------------------------------------------------
extern "C" void kernel_launch(void* const* d_in, const int* in_sizes, int n_in,
                              void* d_out, int out_size) {
    const float* x  = (const float*)d_in[0];
    const float* w  = (const float*)d_in[1];
    const float* ev = (const float*)d_in[2];
    const int*   er = (const int*)d_in[3];
    const int*   ec = (const int*)d_in[4];
    float*       out = (float*)d_out;
    const int E  = in_sizes[2];
    const int n4 = (NN * DD) / 4;

    zero_kernel<<<(n4 + 255) / 256, 256>>>((float4*)out, n4);
    gemm_kernel<<<dim3(DD / 128, (NN + 127) / 128), 256>>>(x, w);
    spmm_kernel<<<(E + 7) / 8, 256>>>(ev, er, ec, out, E);
    relu_kernel<<<(n4 + 255) / 256, 256>>>((float4*)out, n4);
}

// round 5
// speedup vs baseline: 1.6731x; 1.6731x over previous
#include <cuda_runtime.h>
#include <cstdint>

#define NN 100000
#define DD 256
#define NE 3200000
#define SCAN_B 512
#define SCAN_NBLK ((NN + SCAN_B - 1) / SCAN_B)   // 196

// ---------------------------------------------------------------------------
// Device scratch (allocation-free rule: __device__ globals)
// ---------------------------------------------------------------------------
__device__ float g_support[(size_t)NN * DD];   // x @ W
__device__ int   g_count[NN];                  // per-row edge count
__device__ int   g_start[NN + 1];              // CSR row starts (exclusive scan)
__device__ int   g_pos[NN];                    // scatter cursors
__device__ int   g_bsum[SCAN_NBLK];            // scan block totals
__device__ int   g_scol[NE];                   // edges sorted by row: col
__device__ float g_sval[NE];                   // edges sorted by row: val

// ---------------------------------------------------------------------------
// GEMM: support = x @ W   (128x128 tile, 8x8 microtile, unchanged from R2)
// ---------------------------------------------------------------------------
__global__ void __launch_bounds__(256) gemm_kernel(const float* __restrict__ A,
                                                   const float* __restrict__ B) {
    __shared__ float As[8][128];
    __shared__ float Bs[8][128];

    const int tid  = threadIdx.x;
    const int tx   = tid & 15;
    const int ty   = tid >> 4;
    const int row0 = blockIdx.y * 128;
    const int col0 = blockIdx.x * 128;

    const int a_row = tid >> 1;
    const int a_k4  = (tid & 1) * 4;
    const int b_k   = tid >> 5;
    const int b_c   = (tid & 31) * 4;

    float acc[8][8];
#pragma unroll
    for (int i = 0; i < 8; i++)
#pragma unroll
        for (int j = 0; j < 8; j++) acc[i][j] = 0.0f;

    for (int k0 = 0; k0 < DD; k0 += 8) {
        int gr = row0 + a_row;
        gr = gr < NN ? gr : NN - 1;
        float4 av = *(const float4*)(A + (size_t)gr * DD + k0 + a_k4);
        As[a_k4 + 0][a_row] = av.x;
        As[a_k4 + 1][a_row] = av.y;
        As[a_k4 + 2][a_row] = av.z;
        As[a_k4 + 3][a_row] = av.w;
        float4 bv = *(const float4*)(B + (size_t)(k0 + b_k) * DD + col0 + b_c);
        *(float4*)&Bs[b_k][b_c] = bv;
        __syncthreads();

#pragma unroll
        for (int kk = 0; kk < 8; kk++) {
            float4 a0 = *(const float4*)&As[kk][ty * 4];
            float4 a1 = *(const float4*)&As[kk][64 + ty * 4];
            float4 b0 = *(const float4*)&Bs[kk][tx * 4];
            float4 b1 = *(const float4*)&Bs[kk][64 + tx * 4];
            float a[8] = {a0.x, a0.y, a0.z, a0.w, a1.x, a1.y, a1.z, a1.w};
            float b[8] = {b0.x, b0.y, b0.z, b0.w, b1.x, b1.y, b1.z, b1.w};
#pragma unroll
            for (int i = 0; i < 8; i++)
#pragma unroll
                for (int j = 0; j < 8; j++) acc[i][j] += a[i] * b[j];
        }
        __syncthreads();
    }

#pragma unroll
    for (int i = 0; i < 8; i++) {
        int r = row0 + ((i < 4) ? (ty * 4 + i) : (64 + ty * 4 + (i - 4)));
        if (r < NN) {
            float4 v0 = make_float4(acc[i][0], acc[i][1], acc[i][2], acc[i][3]);
            float4 v1 = make_float4(acc[i][4], acc[i][5], acc[i][6], acc[i][7]);
            *(float4*)(g_support + (size_t)r * DD + col0 + tx * 4) = v0;
            *(float4*)(g_support + (size_t)r * DD + col0 + 64 + tx * 4) = v1;
        }
    }
}

// ---------------------------------------------------------------------------
// CSR build: histogram -> exclusive scan (3 kernels) -> scatter
// ---------------------------------------------------------------------------
__global__ void __launch_bounds__(256) zero_count_kernel() {
    int i = blockIdx.x * 256 + threadIdx.x;
    if (i < NN) g_count[i] = 0;
}

__global__ void __launch_bounds__(256) hist_kernel(const int* __restrict__ er, int E) {
    int e = blockIdx.x * 256 + threadIdx.x;
    if (e < E) atomicAdd(&g_count[er[e]], 1);
}

// Per-block Hillis-Steele exclusive scan; block totals to g_bsum.
__global__ void __launch_bounds__(SCAN_B) scan1_kernel() {
    __shared__ int sh[SCAN_B];
    int i = blockIdx.x * SCAN_B + threadIdx.x;
    int v = (i < NN) ? g_count[i] : 0;
    sh[threadIdx.x] = v;
    __syncthreads();
#pragma unroll
    for (int off = 1; off < SCAN_B; off <<= 1) {
        int t = (threadIdx.x >= off) ? sh[threadIdx.x - off] : 0;
        __syncthreads();
        sh[threadIdx.x] += t;
        __syncthreads();
    }
    int incl = sh[threadIdx.x];
    if (i < NN) g_start[i] = incl - v;            // exclusive within block
    if (threadIdx.x == SCAN_B - 1) g_bsum[blockIdx.x] = incl;
}

// Scan the 196 block totals (single block).
__global__ void __launch_bounds__(256) scan2_kernel() {
    __shared__ int sh[256];
    int t = threadIdx.x;
    int v = (t < SCAN_NBLK) ? g_bsum[t] : 0;
    sh[t] = v;
    __syncthreads();
#pragma unroll
    for (int off = 1; off < 256; off <<= 1) {
        int p = (t >= off) ? sh[t - off] : 0;
        __syncthreads();
        sh[t] += p;
        __syncthreads();
    }
    if (t < SCAN_NBLK) g_bsum[t] = sh[t] - v;     // exclusive
}

// Add block offsets; also init scatter cursors and the sentinel.
__global__ void __launch_bounds__(256) scan3_kernel(int E) {
    int i = blockIdx.x * 256 + threadIdx.x;
    if (i < NN) {
        int s = g_start[i] + g_bsum[i / SCAN_B];
        g_start[i] = s;
        g_pos[i]   = s;
    } else if (i == NN) {
        g_start[NN] = E;
    }
}

__global__ void __launch_bounds__(256) scatter_kernel(const float* __restrict__ ev,
                                                      const int* __restrict__ er,
                                                      const int* __restrict__ ec,
                                                      int E) {
    int e = blockIdx.x * 256 + threadIdx.x;
    if (e < E) {
        int p = atomicAdd(&g_pos[er[e]], 1);
        g_scol[p] = ec[e];
        g_sval[p] = ev[e];
    }
}

// ---------------------------------------------------------------------------
// Aggregate + ReLU: one warp per row, full row accumulated in registers.
// ---------------------------------------------------------------------------
__global__ void __launch_bounds__(256) aggregate_kernel(float* __restrict__ out) {
    const int row  = (blockIdx.x * 256 + threadIdx.x) >> 5;
    const int lane = threadIdx.x & 31;
    if (row >= NN) return;

    const int s = g_start[row];
    const int e = g_start[row + 1];

    float4 a0 = make_float4(0.f, 0.f, 0.f, 0.f);
    float4 a1 = make_float4(0.f, 0.f, 0.f, 0.f);

    for (int base = s; base < e; base += 32) {
        const int idx = base + lane;
        const int   c = (idx < e) ? g_scol[idx] : 0;
        const float v = (idx < e) ? g_sval[idx] : 0.f;
        const int   n = min(32, e - base);
        for (int j = 0; j < n; j++) {
            const int   cc = __shfl_sync(0xffffffffu, c, j);
            const float vv = __shfl_sync(0xffffffffu, v, j);
            const float4* sp = (const float4*)(g_support + (size_t)cc * DD);
            float4 m0 = __ldg(sp + lane);
            float4 m1 = __ldg(sp + lane + 32);
            a0.x += vv * m0.x; a0.y += vv * m0.y; a0.z += vv * m0.z; a0.w += vv * m0.w;
            a1.x += vv * m1.x; a1.y += vv * m1.y; a1.z += vv * m1.z; a1.w += vv * m1.w;
        }
    }

    a0.x = fmaxf(a0.x, 0.f); a0.y = fmaxf(a0.y, 0.f);
    a0.z = fmaxf(a0.z, 0.f); a0.w = fmaxf(a0.w, 0.f);
    a1.x = fmaxf(a1.x, 0.f); a1.y = fmaxf(a1.y, 0.f);
    a1.z = fmaxf(a1.z, 0.f); a1.w = fmaxf(a1.w, 0.f);

    float4* o = (float4*)(out + (size_t)row * DD);
    o[lane]      = a0;
    o[lane + 32] = a1;
}

// ---------------------------------------------------------------------------
// Launch
// ---------------------------------------------------------------------------
extern "C" void kernel_launch(void* const* d_in, const int* in_sizes, int n_in,
                              void* d_out, int out_size) {
    const float* x  = (const float*)d_in[0];
    const float* w  = (const float*)d_in[1];
    const float* ev = (const float*)d_in[2];
    const int*   er = (const int*)d_in[3];
    const int*   ec = (const int*)d_in[4];
    float*       out = (float*)d_out;
    const int E = in_sizes[2];

    const int gE  = (E + 255) / 256;
    const int gN  = (NN + 255) / 256;
    const int gN1 = (NN + 1 + 255) / 256;

    gemm_kernel<<<dim3(DD / 128, (NN + 127) / 128), 256>>>(x, w);
    zero_count_kernel<<<gN, 256>>>();
    hist_kernel<<<gE, 256>>>(er, E);
    scan1_kernel<<<SCAN_NBLK, SCAN_B>>>();
    scan2_kernel<<<1, 256>>>();
    scan3_kernel<<<gN1, 256>>>(E);
    scatter_kernel<<<gE, 256>>>(ev, er, ec, E);
    aggregate_kernel<<<(NN * 32 + 255) / 256, 256>>>(out);
}

// round 8
// speedup vs baseline: 3.2470x; 1.9407x over previous
#include <cuda_runtime.h>
#include <cstdint>

#define NN 100000
#define DD 256
#define NE 3200000
#define SCAN_B 512
#define SCAN_NBLK ((NN + SCAN_B - 1) / SCAN_B)   // 196

// ---------------------------------------------------------------------------
// Device scratch (allocation-free rule: __device__ globals)
// ---------------------------------------------------------------------------
__device__ float g_support[(size_t)NN * DD];   // x @ W
__device__ int   g_count[NN];                  // per-row edge count
__device__ int   g_start[NN + 1];              // CSR row starts (exclusive scan)
__device__ int   g_pos[NN];                    // scatter cursors
__device__ int   g_bsum[SCAN_NBLK];            // scan block totals
__device__ int   g_scol[NE];                   // edges sorted by row: col
__device__ float g_sval[NE];                   // edges sorted by row: val

// ---------------------------------------------------------------------------
// tf32 tensor-core GEMM: support[NN,256] = x[NN,256] @ W[256,256]
// 128x128 block tile, 8 warps in 2(M)x4(N), warp tile 64x32, K-chunk 32.
// mma.sync.aligned.m16n8k8.row.col.f32.tf32.tf32.f32
// ---------------------------------------------------------------------------
#define AS_STRIDE 36    // 128 rows x 32+4 pad: frag reads hit all 32 banks
#define BS_STRIDE 132   // 32 k-rows x 128+4 pad

__device__ __forceinline__ unsigned f2tf(float f) {
    unsigned r;
    asm("cvt.rna.tf32.f32 %0, %1;" : "=r"(r) : "f"(f));
    return r;
}

__global__ void __launch_bounds__(256, 2) gemm_tc_kernel(const float* __restrict__ A,
                                                         const float* __restrict__ B) {
    __shared__ unsigned As[128 * AS_STRIDE];   // [m][k] tf32 bits
    __shared__ unsigned Bs[32 * BS_STRIDE];    // [k][n] tf32 bits

    const int tid  = threadIdx.x;
    const int warp = tid >> 5;
    const int lane = tid & 31;
    const int g    = lane >> 2;   // 0..7
    const int l    = lane & 3;    // 0..3

    const int wm = warp & 1;      // 0..1  -> 64-row slab
    const int wn = warp >> 1;     // 0..3  -> 32-col slab

    const int row0 = blockIdx.y * 128;
    const int col0 = blockIdx.x * 128;

    float c[4][4][4];   // [m-tile][n-tile][frag]
#pragma unroll
    for (int i = 0; i < 4; i++)
#pragma unroll
        for (int j = 0; j < 4; j++)
#pragma unroll
            for (int q = 0; q < 4; q++) c[i][j][q] = 0.0f;

    for (int k0 = 0; k0 < DD; k0 += 32) {
        // --- load A tile: each warp covers rows [warp*16, warp*16+16) ---
#pragma unroll
        for (int i = 0; i < 4; i++) {
            const int rl = warp * 16 + i * 4 + (lane >> 3);   // 0..127
            int gr = row0 + rl;
            gr = gr < NN ? gr : NN - 1;
            const int f4 = (lane & 7) * 4;                    // k within chunk
            float4 v = *(const float4*)(A + (size_t)gr * DD + k0 + f4);
            unsigned* d = &As[rl * AS_STRIDE + f4];
            d[0] = f2tf(v.x); d[1] = f2tf(v.y); d[2] = f2tf(v.z); d[3] = f2tf(v.w);
        }
        // --- load B tile: warp w covers k-rows {w*4 .. w*4+3}, lane covers n ---
#pragma unroll
        for (int i = 0; i < 4; i++) {
            const int kl = warp * 4 + i;                      // 0..31
            float4 v = *(const float4*)(B + (size_t)(k0 + kl) * DD + col0 + lane * 4);
            unsigned* d = &Bs[kl * BS_STRIDE + lane * 4];
            d[0] = f2tf(v.x); d[1] = f2tf(v.y); d[2] = f2tf(v.z); d[3] = f2tf(v.w);
        }
        __syncthreads();

#pragma unroll
        for (int kk = 0; kk < 32; kk += 8) {
            unsigned af[4][4];
#pragma unroll
            for (int i = 0; i < 4; i++) {
                const int mr = wm * 64 + i * 16 + g;
                af[i][0] = As[(mr)     * AS_STRIDE + kk + l];
                af[i][1] = As[(mr + 8) * AS_STRIDE + kk + l];
                af[i][2] = As[(mr)     * AS_STRIDE + kk + l + 4];
                af[i][3] = As[(mr + 8) * AS_STRIDE + kk + l + 4];
            }
            unsigned bf[4][2];
#pragma unroll
            for (int j = 0; j < 4; j++) {
                const int nc = wn * 32 + j * 8 + g;
                bf[j][0] = Bs[(kk + l)     * BS_STRIDE + nc];
                bf[j][1] = Bs[(kk + l + 4) * BS_STRIDE + nc];
            }
#pragma unroll
            for (int i = 0; i < 4; i++)
#pragma unroll
                for (int j = 0; j < 4; j++) {
                    asm volatile(
                        "mma.sync.aligned.m16n8k8.row.col.f32.tf32.tf32.f32 "
                        "{%0,%1,%2,%3}, {%4,%5,%6,%7}, {%8,%9}, {%0,%1,%2,%3};"
                        : "+f"(c[i][j][0]), "+f"(c[i][j][1]),
                          "+f"(c[i][j][2]), "+f"(c[i][j][3])
                        : "r"(af[i][0]), "r"(af[i][1]), "r"(af[i][2]), "r"(af[i][3]),
                          "r"(bf[j][0]), "r"(bf[j][1]));
                }
        }
        __syncthreads();
    }

    // --- epilogue: c0,c1 -> (row g, col 2l), c2,c3 -> (row g+8) ---
#pragma unroll
    for (int i = 0; i < 4; i++) {
        const int r_lo = row0 + wm * 64 + i * 16 + g;
        const int r_hi = r_lo + 8;
#pragma unroll
        for (int j = 0; j < 4; j++) {
            const int cc = col0 + wn * 32 + j * 8 + 2 * l;
            if (r_lo < NN)
                *(float2*)(g_support + (size_t)r_lo * DD + cc) =
                    make_float2(c[i][j][0], c[i][j][1]);
            if (r_hi < NN)
                *(float2*)(g_support + (size_t)r_hi * DD + cc) =
                    make_float2(c[i][j][2], c[i][j][3]);
        }
    }
}

// ---------------------------------------------------------------------------
// CSR build: histogram -> exclusive scan (3 kernels) -> scatter
// ---------------------------------------------------------------------------
__global__ void __launch_bounds__(256) zero_count_kernel() {
    int i = blockIdx.x * 256 + threadIdx.x;
    if (i < NN) g_count[i] = 0;
}

__global__ void __launch_bounds__(256) hist_kernel(const int* __restrict__ er, int E) {
    int e = blockIdx.x * 256 + threadIdx.x;
    if (e < E) atomicAdd(&g_count[er[e]], 1);
}

__global__ void __launch_bounds__(SCAN_B) scan1_kernel() {
    __shared__ int sh[SCAN_B];
    int i = blockIdx.x * SCAN_B + threadIdx.x;
    int v = (i < NN) ? g_count[i] : 0;
    sh[threadIdx.x] = v;
    __syncthreads();
#pragma unroll
    for (int off = 1; off < SCAN_B; off <<= 1) {
        int t = (threadIdx.x >= off) ? sh[threadIdx.x - off] : 0;
        __syncthreads();
        sh[threadIdx.x] += t;
        __syncthreads();
    }
    int incl = sh[threadIdx.x];
    if (i < NN) g_start[i] = incl - v;
    if (threadIdx.x == SCAN_B - 1) g_bsum[blockIdx.x] = incl;
}

__global__ void __launch_bounds__(256) scan2_kernel() {
    __shared__ int sh[256];
    int t = threadIdx.x;
    int v = (t < SCAN_NBLK) ? g_bsum[t] : 0;
    sh[t] = v;
    __syncthreads();
#pragma unroll
    for (int off = 1; off < 256; off <<= 1) {
        int p = (t >= off) ? sh[t - off] : 0;
        __syncthreads();
        sh[t] += p;
        __syncthreads();
    }
    if (t < SCAN_NBLK) g_bsum[t] = sh[t] - v;
}

__global__ void __launch_bounds__(256) scan3_kernel(int E) {
    int i = blockIdx.x * 256 + threadIdx.x;
    if (i < NN) {
        int s = g_start[i] + g_bsum[i / SCAN_B];
        g_start[i] = s;
        g_pos[i]   = s;
    } else if (i == NN) {
        g_start[NN] = E;
    }
}

__global__ void __launch_bounds__(256) scatter_kernel(const float* __restrict__ ev,
                                                      const int* __restrict__ er,
                                                      const int* __restrict__ ec,
                                                      int E) {
    int e = blockIdx.x * 256 + threadIdx.x;
    if (e < E) {
        int p = atomicAdd(&g_pos[er[e]], 1);
        g_scol[p] = ec[e];
        g_sval[p] = ev[e];
    }
}

// ---------------------------------------------------------------------------
// Aggregate + ReLU: one warp per row, full row accumulated in registers.
// ---------------------------------------------------------------------------
__global__ void __launch_bounds__(256) aggregate_kernel(float* __restrict__ out) {
    const int row  = (blockIdx.x * 256 + threadIdx.x) >> 5;
    const int lane = threadIdx.x & 31;
    if (row >= NN) return;

    const int s = g_start[row];
    const int e = g_start[row + 1];

    float4 a0 = make_float4(0.f, 0.f, 0.f, 0.f);
    float4 a1 = make_float4(0.f, 0.f, 0.f, 0.f);

    for (int base = s; base < e; base += 32) {
        const int idx = base + lane;
        const int   c = (idx < e) ? g_scol[idx] : 0;
        const float v = (idx < e) ? g_sval[idx] : 0.f;
        const int   n = min(32, e - base);
        for (int j = 0; j < n; j++) {
            const int   cc = __shfl_sync(0xffffffffu, c, j);
            const float vv = __shfl_sync(0xffffffffu, v, j);
            const float4* sp = (const float4*)(g_support + (size_t)cc * DD);
            float4 m0 = __ldg(sp + lane);
            float4 m1 = __ldg(sp + lane + 32);
            a0.x += vv * m0.x; a0.y += vv * m0.y; a0.z += vv * m0.z; a0.w += vv * m0.w;
            a1.x += vv * m1.x; a1.y += vv * m1.y; a1.z += vv * m1.z; a1.w += vv * m1.w;
        }
    }

    a0.x = fmaxf(a0.x, 0.f); a0.y = fmaxf(a0.y, 0.f);
    a0.z = fmaxf(a0.z, 0.f); a0.w = fmaxf(a0.w, 0.f);
    a1.x = fmaxf(a1.x, 0.f); a1.y = fmaxf(a1.y, 0.f);
    a1.z = fmaxf(a1.z, 0.f); a1.w = fmaxf(a1.w, 0.f);

    float4* o = (float4*)(out + (size_t)row * DD);
    o[lane]      = a0;
    o[lane + 32] = a1;
}

// ---------------------------------------------------------------------------
// Launch
// ---------------------------------------------------------------------------
extern "C" void kernel_launch(void* const* d_in, const int* in_sizes, int n_in,
                              void* d_out, int out_size) {
    const float* x  = (const float*)d_in[0];
    const float* w  = (const float*)d_in[1];
    const float* ev = (const float*)d_in[2];
    const int*   er = (const int*)d_in[3];
    const int*   ec = (const int*)d_in[4];
    float*       out = (float*)d_out;
    const int E = in_sizes[2];

    const int gE  = (E + 255) / 256;
    const int gN  = (NN + 255) / 256;
    const int gN1 = (NN + 1 + 255) / 256;

    gemm_tc_kernel<<<dim3(DD / 128, (NN + 127) / 128), 256>>>(x, w);
    zero_count_kernel<<<gN, 256>>>();
    hist_kernel<<<gE, 256>>>(er, E);
    scan1_kernel<<<SCAN_NBLK, SCAN_B>>>();
    scan2_kernel<<<1, 256>>>();
    scan3_kernel<<<gN1, 256>>>(E);
    scatter_kernel<<<gE, 256>>>(ev, er, ec, E);
    aggregate_kernel<<<(NN * 32 + 255) / 256, 256>>>(out);
}

// round 10
// speedup vs baseline: 4.7155x; 1.4523x over previous
#include <cuda_runtime.h>
#include <cuda_fp16.h>
#include <cstdint>

#define NN 100000
#define DD 256
#define NE 3200000
#define SCAN_B 512
#define SCAN_NBLK ((NN + SCAN_B - 1) / SCAN_B)   // 196

// ---------------------------------------------------------------------------
// Device scratch (allocation-free rule: __device__ globals)
// ---------------------------------------------------------------------------
__device__ __half g_support[(size_t)NN * DD];  // x @ W, fp16 (halves gather bytes)
__device__ int    g_count[NN];                 // per-row edge count
__device__ int    g_start[NN + 1];             // CSR row starts (exclusive scan)
__device__ int    g_pos[NN];                   // scatter cursors
__device__ int    g_bsum[SCAN_NBLK];           // scan block totals
__device__ int2   g_edge[NE];                  // edges sorted by row: (col, val bits)

// ---------------------------------------------------------------------------
// tf32 tensor-core GEMM: support[NN,256] = x[NN,256] @ W[256,256]
// 128x128 block tile, 8 warps in 2(M)x4(N), warp tile 64x32, K-chunk 32.
// Epilogue converts to fp16.
// ---------------------------------------------------------------------------
#define AS_STRIDE 36
#define BS_STRIDE 132

__device__ __forceinline__ unsigned f2tf(float f) {
    unsigned r;
    asm("cvt.rna.tf32.f32 %0, %1;" : "=r"(r) : "f"(f));
    return r;
}

__global__ void __launch_bounds__(256, 2) gemm_tc_kernel(const float* __restrict__ A,
                                                         const float* __restrict__ B) {
    __shared__ unsigned As[128 * AS_STRIDE];   // [m][k] tf32 bits
    __shared__ unsigned Bs[32 * BS_STRIDE];    // [k][n] tf32 bits

    const int tid  = threadIdx.x;
    const int warp = tid >> 5;
    const int lane = tid & 31;
    const int g    = lane >> 2;
    const int l    = lane & 3;

    const int wm = warp & 1;
    const int wn = warp >> 1;

    const int row0 = blockIdx.y * 128;
    const int col0 = blockIdx.x * 128;

    float c[4][4][4];
#pragma unroll
    for (int i = 0; i < 4; i++)
#pragma unroll
        for (int j = 0; j < 4; j++)
#pragma unroll
            for (int q = 0; q < 4; q++) c[i][j][q] = 0.0f;

    for (int k0 = 0; k0 < DD; k0 += 32) {
#pragma unroll
        for (int i = 0; i < 4; i++) {
            const int rl = warp * 16 + i * 4 + (lane >> 3);
            int gr = row0 + rl;
            gr = gr < NN ? gr : NN - 1;
            const int f4 = (lane & 7) * 4;
            float4 v = *(const float4*)(A + (size_t)gr * DD + k0 + f4);
            unsigned* d = &As[rl * AS_STRIDE + f4];
            d[0] = f2tf(v.x); d[1] = f2tf(v.y); d[2] = f2tf(v.z); d[3] = f2tf(v.w);
        }
#pragma unroll
        for (int i = 0; i < 4; i++) {
            const int kl = warp * 4 + i;
            float4 v = *(const float4*)(B + (size_t)(k0 + kl) * DD + col0 + lane * 4);
            unsigned* d = &Bs[kl * BS_STRIDE + lane * 4];
            d[0] = f2tf(v.x); d[1] = f2tf(v.y); d[2] = f2tf(v.z); d[3] = f2tf(v.w);
        }
        __syncthreads();

#pragma unroll
        for (int kk = 0; kk < 32; kk += 8) {
            unsigned af[4][4];
#pragma unroll
            for (int i = 0; i < 4; i++) {
                const int mr = wm * 64 + i * 16 + g;
                af[i][0] = As[(mr)     * AS_STRIDE + kk + l];
                af[i][1] = As[(mr + 8) * AS_STRIDE + kk + l];
                af[i][2] = As[(mr)     * AS_STRIDE + kk + l + 4];
                af[i][3] = As[(mr + 8) * AS_STRIDE + kk + l + 4];
            }
            unsigned bf[4][2];
#pragma unroll
            for (int j = 0; j < 4; j++) {
                const int nc = wn * 32 + j * 8 + g;
                bf[j][0] = Bs[(kk + l)     * BS_STRIDE + nc];
                bf[j][1] = Bs[(kk + l + 4) * BS_STRIDE + nc];
            }
#pragma unroll
            for (int i = 0; i < 4; i++)
#pragma unroll
                for (int j = 0; j < 4; j++) {
                    asm volatile(
                        "mma.sync.aligned.m16n8k8.row.col.f32.tf32.tf32.f32 "
                        "{%0,%1,%2,%3}, {%4,%5,%6,%7}, {%8,%9}, {%0,%1,%2,%3};"
                        : "+f"(c[i][j][0]), "+f"(c[i][j][1]),
                          "+f"(c[i][j][2]), "+f"(c[i][j][3])
                        : "r"(af[i][0]), "r"(af[i][1]), "r"(af[i][2]), "r"(af[i][3]),
                          "r"(bf[j][0]), "r"(bf[j][1]));
                }
        }
        __syncthreads();
    }

    // epilogue: fp32 frags -> fp16 pairs. cols (2l, 2l+1) -> one __half2 store.
#pragma unroll
    for (int i = 0; i < 4; i++) {
        const int r_lo = row0 + wm * 64 + i * 16 + g;
        const int r_hi = r_lo + 8;
#pragma unroll
        for (int j = 0; j < 4; j++) {
            const int cc = col0 + wn * 32 + j * 8 + 2 * l;
            if (r_lo < NN)
                *(__half2*)(g_support + (size_t)r_lo * DD + cc) =
                    __floats2half2_rn(c[i][j][0], c[i][j][1]);
            if (r_hi < NN)
                *(__half2*)(g_support + (size_t)r_hi * DD + cc) =
                    __floats2half2_rn(c[i][j][2], c[i][j][3]);
        }
    }
}

// ---------------------------------------------------------------------------
// CSR build: histogram -> exclusive scan (3 kernels) -> scatter
// ---------------------------------------------------------------------------
__global__ void __launch_bounds__(256) zero_count_kernel() {
    int i = blockIdx.x * 256 + threadIdx.x;
    if (i < NN) g_count[i] = 0;
}

__global__ void __launch_bounds__(256) hist_kernel(const int* __restrict__ er, int E) {
    int e = blockIdx.x * 256 + threadIdx.x;
    if (e < E) atomicAdd(&g_count[er[e]], 1);
}

__global__ void __launch_bounds__(SCAN_B) scan1_kernel() {
    __shared__ int sh[SCAN_B];
    int i = blockIdx.x * SCAN_B + threadIdx.x;
    int v = (i < NN) ? g_count[i] : 0;
    sh[threadIdx.x] = v;
    __syncthreads();
#pragma unroll
    for (int off = 1; off < SCAN_B; off <<= 1) {
        int t = (threadIdx.x >= off) ? sh[threadIdx.x - off] : 0;
        __syncthreads();
        sh[threadIdx.x] += t;
        __syncthreads();
    }
    int incl = sh[threadIdx.x];
    if (i < NN) g_start[i] = incl - v;
    if (threadIdx.x == SCAN_B - 1) g_bsum[blockIdx.x] = incl;
}

__global__ void __launch_bounds__(256) scan2_kernel() {
    __shared__ int sh[256];
    int t = threadIdx.x;
    int v = (t < SCAN_NBLK) ? g_bsum[t] : 0;
    sh[t] = v;
    __syncthreads();
#pragma unroll
    for (int off = 1; off < 256; off <<= 1) {
        int p = (t >= off) ? sh[t - off] : 0;
        __syncthreads();
        sh[t] += p;
        __syncthreads();
    }
    if (t < SCAN_NBLK) g_bsum[t] = sh[t] - v;
}

__global__ void __launch_bounds__(256) scan3_kernel(int E) {
    int i = blockIdx.x * 256 + threadIdx.x;
    if (i < NN) {
        int s = g_start[i] + g_bsum[i / SCAN_B];
        g_start[i] = s;
        g_pos[i]   = s;
    } else if (i == NN) {
        g_start[NN] = E;
    }
}

__global__ void __launch_bounds__(256) scatter_kernel(const float* __restrict__ ev,
                                                      const int* __restrict__ er,
                                                      const int* __restrict__ ec,
                                                      int E) {
    int e = blockIdx.x * 256 + threadIdx.x;
    if (e < E) {
        int p = atomicAdd(&g_pos[er[e]], 1);
        g_edge[p] = make_int2(ec[e], __float_as_int(ev[e]));
    }
}

// ---------------------------------------------------------------------------
// Aggregate + ReLU: one warp per row, fp16 support gathers, fp32 accumulate.
// Per edge: ONE float4 load per lane (8 halves) -> 512B/edge L2 traffic.
// ---------------------------------------------------------------------------
__global__ void __launch_bounds__(256) aggregate_kernel(float* __restrict__ out) {
    const int row  = (blockIdx.x * 256 + threadIdx.x) >> 5;
    const int lane = threadIdx.x & 31;
    if (row >= NN) return;

    const int s = g_start[row];
    const int e = g_start[row + 1];

    float a[8];
#pragma unroll
    for (int q = 0; q < 8; q++) a[q] = 0.0f;

    for (int base = s; base < e; base += 32) {
        const int idx = base + lane;
        int2 ed = (idx < e) ? g_edge[idx] : make_int2(0, 0);
        const int n = min(32, e - base);
        for (int j = 0; j < n; j++) {
            const int   cc = __shfl_sync(0xffffffffu, ed.x, j);
            const float vv = __int_as_float(__shfl_sync(0xffffffffu, ed.y, j));
            // 8 halves for this lane's columns [lane*8, lane*8+8)
            const float4* sp = (const float4*)(g_support + (size_t)cc * DD);
            float4 raw = __ldg(sp + lane);
            const __half2* h = (const __half2*)&raw;
            float2 f0 = __half22float2(h[0]);
            float2 f1 = __half22float2(h[1]);
            float2 f2 = __half22float2(h[2]);
            float2 f3 = __half22float2(h[3]);
            a[0] += vv * f0.x; a[1] += vv * f0.y;
            a[2] += vv * f1.x; a[3] += vv * f1.y;
            a[4] += vv * f2.x; a[5] += vv * f2.y;
            a[6] += vv * f3.x; a[7] += vv * f3.y;
        }
    }

#pragma unroll
    for (int q = 0; q < 8; q++) a[q] = fmaxf(a[q], 0.0f);

    float4* o = (float4*)(out + (size_t)row * DD + lane * 8);
    o[0] = make_float4(a[0], a[1], a[2], a[3]);
    o[1] = make_float4(a[4], a[5], a[6], a[7]);
}

// ---------------------------------------------------------------------------
// Launch
// ---------------------------------------------------------------------------
extern "C" void kernel_launch(void* const* d_in, const int* in_sizes, int n_in,
                              void* d_out, int out_size) {
    const float* x  = (const float*)d_in[0];
    const float* w  = (const float*)d_in[1];
    const float* ev = (const float*)d_in[2];
    const int*   er = (const int*)d_in[3];
    const int*   ec = (const int*)d_in[4];
    float*       out = (float*)d_out;
    const int E = in_sizes[2];

    const int gE  = (E + 255) / 256;
    const int gN  = (NN + 255) / 256;
    const int gN1 = (NN + 1 + 255) / 256;

    gemm_tc_kernel<<<dim3(DD / 128, (NN + 127) / 128), 256>>>(x, w);
    zero_count_kernel<<<gN, 256>>>();
    hist_kernel<<<gE, 256>>>(er, E);
    scan1_kernel<<<SCAN_NBLK, SCAN_B>>>();
    scan2_kernel<<<1, 256>>>();
    scan3_kernel<<<gN1, 256>>>(E);
    scatter_kernel<<<gE, 256>>>(ev, er, ec, E);
    aggregate_kernel<<<(NN * 32 + 255) / 256, 256>>>(out);
}